// round 1
// baseline (speedup 1.0000x reference)
#include <cuda_runtime.h>
#include <math.h>

#define T_TOK 2048
#define H_DIM 2048
#define E_NUM 32
#define I_DIM 768
#define TOPK  8
#define NASSIGN (T_TOK * TOPK)

#define BM 64
#define BN 64
#define BK 16
#define BMP (BM + 4)
#define BNP (BN + 4)

// ---------------- scratch (static __device__, no allocations) ----------------
__device__ int   g_topk_id[T_TOK][TOPK];
__device__ float g_topk_w[T_TOK][TOPK];
__device__ int   g_cnt[E_NUM];
__device__ int   g_off[E_NUM + 1];
__device__ int   g_cur[E_NUM];
__device__ int   g_slot_tok[NASSIGN];
__device__ float g_slot_w[NASSIGN];
__device__ float g_act[NASSIGN][I_DIM];   // ~50 MB scratch for silu(g)*u*w

// ---------------- meta reset ----------------
__global__ void zero_meta_kernel() {
    int i = threadIdx.x;
    if (i < E_NUM) { g_cnt[i] = 0; g_cur[i] = 0; }
}

// ---------------- router: logits -> top8 -> softmax(top8) ----------------
__global__ void router_kernel(const float* __restrict__ hs,
                              const float* __restrict__ gw) {
    int t = blockIdx.x;
    __shared__ float part[128][E_NUM];
    __shared__ float sl[E_NUM];

    float acc[E_NUM];
#pragma unroll
    for (int e = 0; e < E_NUM; e++) acc[e] = 0.f;

    const float* hrow = hs + (size_t)t * H_DIM;
    for (int h = threadIdx.x; h < H_DIM; h += 128) {
        float x = hrow[h];
#pragma unroll
        for (int e = 0; e < E_NUM; e++) acc[e] += x * gw[e * H_DIM + h];
    }
#pragma unroll
    for (int e = 0; e < E_NUM; e++) part[threadIdx.x][e] = acc[e];
    __syncthreads();

    if (threadIdx.x < E_NUM) {
        float s = 0.f;
        for (int i = 0; i < 128; i++) s += part[i][threadIdx.x];
        sl[threadIdx.x] = s;
    }
    __syncthreads();

    if (threadIdx.x == 0) {
        unsigned mask = 0;
        int ids[TOPK]; float lv[TOPK];
        for (int k = 0; k < TOPK; k++) {
            float best = -3.4e38f; int bi = 0;
            for (int e = 0; e < E_NUM; e++)
                if (!((mask >> e) & 1u) && sl[e] > best) { best = sl[e]; bi = e; }
            mask |= (1u << bi); ids[k] = bi; lv[k] = best;
        }
        // softmax over selected 8 == renormalized top-k of full softmax
        float mx = lv[0], s = 0.f, w[TOPK];
        for (int k = 0; k < TOPK; k++) { w[k] = expf(lv[k] - mx); s += w[k]; }
        float inv = 1.f / s;
        for (int k = 0; k < TOPK; k++) {
            g_topk_id[t][k] = ids[k];
            g_topk_w[t][k]  = w[k] * inv;
            atomicAdd(&g_cnt[ids[k]], 1);
        }
    }
}

// ---------------- exclusive scan over 32 experts ----------------
__global__ void scan_kernel() {
    if (threadIdx.x == 0) {
        int s = 0;
        g_off[0] = 0;
        for (int e = 0; e < E_NUM; e++) { s += g_cnt[e]; g_off[e + 1] = s; }
    }
}

// ---------------- scatter (token,weight) into per-expert lists ----------------
__global__ void scatter_kernel() {
    int t = blockIdx.x * blockDim.x + threadIdx.x;
    if (t >= T_TOK) return;
#pragma unroll
    for (int k = 0; k < TOPK; k++) {
        int e = g_topk_id[t][k];
        float w = g_topk_w[t][k];
        int p = atomicAdd(&g_cur[e], 1);
        int s = g_off[e] + p;
        g_slot_tok[s] = t;
        g_slot_w[s]  = w;
    }
}

// ---------------- grouped GEMM A: act = silu(X Wg^T) * (X Wu^T) * route_w ----
__global__ __launch_bounds__(256) void gateup_kernel(
    const float* __restrict__ hs,
    const float* __restrict__ wg,
    const float* __restrict__ wu)
{
    int e   = blockIdx.z;
    int cnt = g_cnt[e];
    int m0  = blockIdx.y * BM;
    if (m0 >= cnt) return;
    int base = g_off[e];
    int n0   = blockIdx.x * BN;

    __shared__ float As[BK][BMP];
    __shared__ float Bg[BK][BNP];
    __shared__ float Bu[BK][BNP];
    __shared__ int   stok[BM];
    __shared__ float swt[BM];

    int tid = threadIdx.x;
    int lr  = tid >> 2;          // 0..63  (row within tile)
    int lk  = (tid & 3) << 2;    // 0,4,8,12

    if (tid < BM) {
        int r = m0 + tid;
        if (r < cnt) { stok[tid] = g_slot_tok[base + r]; swt[tid] = g_slot_w[base + r]; }
        else         { stok[tid] = 0;                    swt[tid] = 0.f; }
    }
    __syncthreads();

    int tx = tid & 15;
    int ty = tid >> 4;

    float ag[4][4], au[4][4];
#pragma unroll
    for (int i = 0; i < 4; i++)
#pragma unroll
        for (int j = 0; j < 4; j++) { ag[i][j] = 0.f; au[i][j] = 0.f; }

    const float* wge = wg + (size_t)e * I_DIM * H_DIM;
    const float* wue = wu + (size_t)e * I_DIM * H_DIM;
    int atok = stok[lr];

    for (int k0 = 0; k0 < H_DIM; k0 += BK) {
        float4 av = *(const float4*)&hs [(size_t)atok       * H_DIM + k0 + lk];
        float4 gv = *(const float4*)&wge[(size_t)(n0 + lr)  * H_DIM + k0 + lk];
        float4 uv = *(const float4*)&wue[(size_t)(n0 + lr)  * H_DIM + k0 + lk];
        __syncthreads();  // previous iteration done reading smem
        As[lk + 0][lr] = av.x; As[lk + 1][lr] = av.y; As[lk + 2][lr] = av.z; As[lk + 3][lr] = av.w;
        Bg[lk + 0][lr] = gv.x; Bg[lk + 1][lr] = gv.y; Bg[lk + 2][lr] = gv.z; Bg[lk + 3][lr] = gv.w;
        Bu[lk + 0][lr] = uv.x; Bu[lk + 1][lr] = uv.y; Bu[lk + 2][lr] = uv.z; Bu[lk + 3][lr] = uv.w;
        __syncthreads();
#pragma unroll
        for (int kk = 0; kk < BK; kk++) {
            float4 a  = *(const float4*)&As[kk][ty * 4];
            float4 bg = *(const float4*)&Bg[kk][tx * 4];
            float4 bu = *(const float4*)&Bu[kk][tx * 4];
            float aa[4]  = {a.x,  a.y,  a.z,  a.w};
            float bgv[4] = {bg.x, bg.y, bg.z, bg.w};
            float buv[4] = {bu.x, bu.y, bu.z, bu.w};
#pragma unroll
            for (int i = 0; i < 4; i++)
#pragma unroll
                for (int j = 0; j < 4; j++) {
                    ag[i][j] += aa[i] * bgv[j];
                    au[i][j] += aa[i] * buv[j];
                }
        }
    }

    // epilogue: silu(g)*u * routing_weight -> g_act
#pragma unroll
    for (int i = 0; i < 4; i++) {
        int lrow = ty * 4 + i;
        int r = m0 + lrow;
        if (r < cnt) {
            float w = swt[lrow];
            float4 o;
            float g0 = ag[i][0], g1 = ag[i][1], g2 = ag[i][2], g3 = ag[i][3];
            o.x = (g0 / (1.f + expf(-g0))) * au[i][0] * w;
            o.y = (g1 / (1.f + expf(-g1))) * au[i][1] * w;
            o.z = (g2 / (1.f + expf(-g2))) * au[i][2] * w;
            o.w = (g3 / (1.f + expf(-g3))) * au[i][3] * w;
            *(float4*)&g_act[base + r][n0 + tx * 4] = o;
        }
    }
}

// ---------------- grouped GEMM B: out += act Wd^T (atomic accumulate) --------
__global__ __launch_bounds__(256) void down_kernel(
    const float* __restrict__ wd,
    float* __restrict__ out)
{
    int e   = blockIdx.z;
    int cnt = g_cnt[e];
    int m0  = blockIdx.y * BM;
    if (m0 >= cnt) return;
    int base = g_off[e];
    int n0   = blockIdx.x * BN;

    __shared__ float As[BK][BMP];
    __shared__ float Bs[BK][BNP];
    __shared__ int   stok[BM];

    int tid = threadIdx.x;
    int lr  = tid >> 2;
    int lk  = (tid & 3) << 2;

    if (tid < BM) {
        int r = m0 + tid;
        stok[tid] = (r < cnt) ? g_slot_tok[base + r] : 0;
    }

    int tx = tid & 15;
    int ty = tid >> 4;

    float acc[4][4];
#pragma unroll
    for (int i = 0; i < 4; i++)
#pragma unroll
        for (int j = 0; j < 4; j++) acc[i][j] = 0.f;

    const float* wde = wd + (size_t)e * H_DIM * I_DIM;
    int arow = base + min(m0 + lr, cnt - 1);   // clamp: stay inside g_act

    for (int k0 = 0; k0 < I_DIM; k0 += BK) {
        float4 av = *(const float4*)&g_act[arow][k0 + lk];
        float4 bv = *(const float4*)&wde[(size_t)(n0 + lr) * I_DIM + k0 + lk];
        __syncthreads();
        As[lk + 0][lr] = av.x; As[lk + 1][lr] = av.y; As[lk + 2][lr] = av.z; As[lk + 3][lr] = av.w;
        Bs[lk + 0][lr] = bv.x; Bs[lk + 1][lr] = bv.y; Bs[lk + 2][lr] = bv.z; Bs[lk + 3][lr] = bv.w;
        __syncthreads();
#pragma unroll
        for (int kk = 0; kk < BK; kk++) {
            float4 a = *(const float4*)&As[kk][ty * 4];
            float4 b = *(const float4*)&Bs[kk][tx * 4];
            float aa[4] = {a.x, a.y, a.z, a.w};
            float bb[4] = {b.x, b.y, b.z, b.w};
#pragma unroll
            for (int i = 0; i < 4; i++)
#pragma unroll
                for (int j = 0; j < 4; j++) acc[i][j] += aa[i] * bb[j];
        }
    }

#pragma unroll
    for (int i = 0; i < 4; i++) {
        int lrow = ty * 4 + i;
        int r = m0 + lrow;
        if (r < cnt) {
            int t = stok[lrow];
            float* orow = out + (size_t)t * H_DIM + n0 + tx * 4;
#pragma unroll
            for (int j = 0; j < 4; j++) atomicAdd(&orow[j], acc[i][j]);
        }
    }
}

// ---------------- launch ----------------
extern "C" void kernel_launch(void* const* d_in, const int* in_sizes, int n_in,
                              void* d_out, int out_size) {
    const float* hs    = (const float*)d_in[0];  // [T, H]
    const float* gw    = (const float*)d_in[1];  // [E, H]
    const float* wgate = (const float*)d_in[2];  // [E, I, H]
    const float* wup   = (const float*)d_in[3];  // [E, I, H]
    const float* wdown = (const float*)d_in[4];  // [E, H, I]
    float* out = (float*)d_out;                  // [T, H]

    cudaMemsetAsync(d_out, 0, (size_t)out_size * sizeof(float));
    zero_meta_kernel<<<1, 32>>>();
    router_kernel<<<T_TOK, 128>>>(hs, gw);
    scan_kernel<<<1, 32>>>();
    scatter_kernel<<<T_TOK / 256, 256>>>();
    gateup_kernel<<<dim3(I_DIM / BN, T_TOK / BM, E_NUM), 256>>>(hs, wgate, wup);
    down_kernel  <<<dim3(H_DIM / BN, T_TOK / BM, E_NUM), 256>>>(wdown, out);
}

// round 3
// speedup vs baseline: 1.5035x; 1.5035x over previous
#include <cuda_runtime.h>
#include <cuda_bf16.h>
#include <math.h>
#include <stdint.h>

#define T_TOK 2048
#define H_DIM 2048
#define E_NUM 32
#define I_DIM 768
#define TOPK  8
#define NASSIGN (T_TOK * TOPK)
#define KCH   32
#define KPAD  44

// ---------------- scratch (static __device__, no allocations) ----------------
__device__ int   g_topk_id[T_TOK][TOPK];
__device__ float g_topk_w[T_TOK][TOPK];
__device__ int   g_cnt[E_NUM];
__device__ int   g_off[E_NUM + 1];
__device__ int   g_cur[E_NUM];
__device__ int   g_slot_tok[NASSIGN];
__device__ float g_slot_w[NASSIGN];
__device__ __nv_bfloat16 g_act_hi[NASSIGN][I_DIM];  // 25 MB
__device__ __nv_bfloat16 g_act_lo[NASSIGN][I_DIM];  // 25 MB

// ---------------- helpers ----------------
// D += A*B for m16n8k16 bf16 (tensor pipe, plain sm_80+ PTX: no 'a' features)
__device__ __forceinline__ void mma16816(float* d, const uint32_t* a, const uint32_t* b) {
    asm volatile(
        "mma.sync.aligned.m16n8k16.row.col.f32.bf16.bf16.f32 "
        "{%0,%1,%2,%3}, {%4,%5,%6,%7}, {%8,%9}, {%0,%1,%2,%3};"
        : "+f"(d[0]), "+f"(d[1]), "+f"(d[2]), "+f"(d[3])
        : "r"(a[0]), "r"(a[1]), "r"(a[2]), "r"(a[3]), "r"(b[0]), "r"(b[1]));
}

// fp32 pair -> packed bf16x2 (hi, lo residual)
__device__ __forceinline__ void split2(float a, float b, uint32_t& hi, uint32_t& lo) {
    __nv_bfloat16 ha = __float2bfloat16(a), hb = __float2bfloat16(b);
    __nv_bfloat16 la = __float2bfloat16(a - __bfloat162float(ha));
    __nv_bfloat16 lb = __float2bfloat16(b - __bfloat162float(hb));
    __nv_bfloat162 ph; ph.x = ha; ph.y = hb; hi = *reinterpret_cast<uint32_t*>(&ph);
    __nv_bfloat162 pl; pl.x = la; pl.y = lb; lo = *reinterpret_cast<uint32_t*>(&pl);
}

// ---------------- meta / router / scan / scatter ----------------
__global__ void zero_meta_kernel() {
    int i = threadIdx.x;
    if (i < E_NUM) { g_cnt[i] = 0; g_cur[i] = 0; }
}

__global__ void router_kernel(const float* __restrict__ hs, const float* __restrict__ gw) {
    int t = blockIdx.x;
    __shared__ float part[128][E_NUM];
    __shared__ float sl[E_NUM];
    float acc[E_NUM];
#pragma unroll
    for (int e = 0; e < E_NUM; e++) acc[e] = 0.f;
    const float* hrow = hs + (size_t)t * H_DIM;
    for (int h = threadIdx.x; h < H_DIM; h += 128) {
        float x = hrow[h];
#pragma unroll
        for (int e = 0; e < E_NUM; e++) acc[e] += x * gw[e * H_DIM + h];
    }
#pragma unroll
    for (int e = 0; e < E_NUM; e++) part[threadIdx.x][e] = acc[e];
    __syncthreads();
    if (threadIdx.x < E_NUM) {
        float s = 0.f;
        for (int i = 0; i < 128; i++) s += part[i][threadIdx.x];
        sl[threadIdx.x] = s;
    }
    __syncthreads();
    if (threadIdx.x == 0) {
        unsigned mask = 0;
        int ids[TOPK]; float lv[TOPK];
        for (int k = 0; k < TOPK; k++) {
            float best = -3.4e38f; int bi = 0;
            for (int e = 0; e < E_NUM; e++)
                if (!((mask >> e) & 1u) && sl[e] > best) { best = sl[e]; bi = e; }
            mask |= (1u << bi); ids[k] = bi; lv[k] = best;
        }
        float mx = lv[0], s = 0.f, w[TOPK];
        for (int k = 0; k < TOPK; k++) { w[k] = expf(lv[k] - mx); s += w[k]; }
        float inv = 1.f / s;
        for (int k = 0; k < TOPK; k++) {
            g_topk_id[t][k] = ids[k];
            g_topk_w[t][k]  = w[k] * inv;
            atomicAdd(&g_cnt[ids[k]], 1);
        }
    }
}

__global__ void scan_kernel() {
    if (threadIdx.x == 0) {
        int s = 0;
        g_off[0] = 0;
        for (int e = 0; e < E_NUM; e++) { s += g_cnt[e]; g_off[e + 1] = s; }
    }
}

__global__ void scatter_kernel() {
    int t = blockIdx.x * blockDim.x + threadIdx.x;
    if (t >= T_TOK) return;
#pragma unroll
    for (int k = 0; k < TOPK; k++) {
        int e = g_topk_id[t][k];
        float w = g_topk_w[t][k];
        int p = atomicAdd(&g_cur[e], 1);
        int s = g_off[e] + p;
        g_slot_tok[s] = t;
        g_slot_w[s]  = w;
    }
}

// ---------------- grouped GEMM A: act = silu(X Wg^T)*(X Wu^T)*w  (HMMA) -----
__global__ __launch_bounds__(256) void gateup_mma_kernel(
    const float* __restrict__ hs,
    const float* __restrict__ wg,
    const float* __restrict__ wu)
{
    int e = blockIdx.z;
    int cnt = g_cnt[e];
    int m0 = blockIdx.y * 128;
    if (m0 >= cnt) return;
    int base = g_off[e];
    int n0 = blockIdx.x * 64;

    __shared__ __nv_bfloat16 AsH[128][KPAD], AsL[128][KPAD];
    __shared__ __nv_bfloat16 BgH[64][KPAD], BgL[64][KPAD];
    __shared__ __nv_bfloat16 BuH[64][KPAD], BuL[64][KPAD];
    __shared__ int   stok[128];
    __shared__ float swt[128];

    int tid = threadIdx.x, wid = tid >> 5, lane = tid & 31;
    int g = lane >> 2, t4 = lane & 3;

    if (tid < 128) {
        int r = m0 + tid;
        int rc = (r < cnt) ? r : (cnt - 1);
        stok[tid] = g_slot_tok[base + rc];
        swt[tid]  = (r < cnt) ? g_slot_w[base + rc] : 0.f;
    }
    __syncthreads();

    // loader mapping: each thread stages 16 contiguous fp32 of A and of B per chunk
    int lr = tid >> 1, lc = (tid & 1) * 16;                       // A row 0..127
    const float* arow = hs + (size_t)stok[lr] * H_DIM + lc;
    int bt = tid & 127, br = bt >> 1, bc = (bt & 1) * 16;         // B row 0..63
    const float* wrow = ((tid >= 128) ? wu : wg)
                        + ((size_t)e * I_DIM + n0 + br) * H_DIM + bc;
    __nv_bfloat16 (*BH)[KPAD] = (tid >= 128) ? BuH : BgH;
    __nv_bfloat16 (*BL)[KPAD] = (tid >= 128) ? BuL : BgL;

    int mr = (wid & 3) * 32, nc = (wid >> 2) * 32;

    float ag[2][4][4] = {}, au[2][4][4] = {};

    float4 av[4], bv[4];
#pragma unroll
    for (int j = 0; j < 4; j++) {
        av[j] = *(const float4*)(arow + 4 * j);
        bv[j] = *(const float4*)(wrow + 4 * j);
    }

    for (int i = 0; i < H_DIM / KCH; i++) {
        __syncthreads();   // previous compute done reading smem
#pragma unroll
        for (int j = 0; j < 4; j++) {
            uint32_t h0, l0, h1, l1;
            split2(av[j].x, av[j].y, h0, l0);
            split2(av[j].z, av[j].w, h1, l1);
            *(uint2*)&AsH[lr][lc + 4 * j] = make_uint2(h0, h1);
            *(uint2*)&AsL[lr][lc + 4 * j] = make_uint2(l0, l1);
            split2(bv[j].x, bv[j].y, h0, l0);
            split2(bv[j].z, bv[j].w, h1, l1);
            *(uint2*)&BH[br][bc + 4 * j] = make_uint2(h0, h1);
            *(uint2*)&BL[br][bc + 4 * j] = make_uint2(l0, l1);
        }
        __syncthreads();
        if (i + 1 < H_DIM / KCH) {   // prefetch next chunk; latency hides under MMA
            int k0 = (i + 1) * KCH;
#pragma unroll
            for (int j = 0; j < 4; j++) {
                av[j] = *(const float4*)(arow + k0 + 4 * j);
                bv[j] = *(const float4*)(wrow + k0 + 4 * j);
            }
        }
#pragma unroll
        for (int kb = 0; kb < KCH; kb += 16) {
            uint32_t aH[2][4], aL[2][4], b0[4][2], b1[4][2];
#pragma unroll
            for (int s = 0; s < 2; s++) {
                int rb = mr + s * 16;
                aH[s][0] = *(const uint32_t*)&AsH[rb + g][kb + 2 * t4];
                aH[s][1] = *(const uint32_t*)&AsH[rb + g + 8][kb + 2 * t4];
                aH[s][2] = *(const uint32_t*)&AsH[rb + g][kb + 2 * t4 + 8];
                aH[s][3] = *(const uint32_t*)&AsH[rb + g + 8][kb + 2 * t4 + 8];
                aL[s][0] = *(const uint32_t*)&AsL[rb + g][kb + 2 * t4];
                aL[s][1] = *(const uint32_t*)&AsL[rb + g + 8][kb + 2 * t4];
                aL[s][2] = *(const uint32_t*)&AsL[rb + g][kb + 2 * t4 + 8];
                aL[s][3] = *(const uint32_t*)&AsL[rb + g + 8][kb + 2 * t4 + 8];
            }
            // ---- gate ----
#pragma unroll
            for (int nn = 0; nn < 4; nn++) {
                int n = nc + nn * 8 + g;
                b0[nn][0] = *(const uint32_t*)&BgH[n][kb + 2 * t4];
                b0[nn][1] = *(const uint32_t*)&BgH[n][kb + 2 * t4 + 8];
                b1[nn][0] = *(const uint32_t*)&BgL[n][kb + 2 * t4];
                b1[nn][1] = *(const uint32_t*)&BgL[n][kb + 2 * t4 + 8];
            }
#pragma unroll
            for (int s = 0; s < 2; s++)
#pragma unroll
                for (int nn = 0; nn < 4; nn++) {
                    mma16816(ag[s][nn], aH[s], b0[nn]);
                    mma16816(ag[s][nn], aH[s], b1[nn]);
                    mma16816(ag[s][nn], aL[s], b0[nn]);
                }
            // ---- up ----
#pragma unroll
            for (int nn = 0; nn < 4; nn++) {
                int n = nc + nn * 8 + g;
                b0[nn][0] = *(const uint32_t*)&BuH[n][kb + 2 * t4];
                b0[nn][1] = *(const uint32_t*)&BuH[n][kb + 2 * t4 + 8];
                b1[nn][0] = *(const uint32_t*)&BuL[n][kb + 2 * t4];
                b1[nn][1] = *(const uint32_t*)&BuL[n][kb + 2 * t4 + 8];
            }
#pragma unroll
            for (int s = 0; s < 2; s++)
#pragma unroll
                for (int nn = 0; nn < 4; nn++) {
                    mma16816(au[s][nn], aH[s], b0[nn]);
                    mma16816(au[s][nn], aH[s], b1[nn]);
                    mma16816(au[s][nn], aL[s], b0[nn]);
                }
        }
    }

    // epilogue: silu(g)*u*route_w -> bf16 hi/lo scratch
#pragma unroll
    for (int s = 0; s < 2; s++) {
#pragma unroll
        for (int half = 0; half < 2; half++) {
            int rl = mr + s * 16 + g + half * 8;
            int r = m0 + rl;
            if (r < cnt) {
                float w = swt[rl];
                size_t slot = (size_t)(base + r);
#pragma unroll
                for (int nn = 0; nn < 4; nn++) {
                    float gv0 = ag[s][nn][half * 2 + 0], gv1 = ag[s][nn][half * 2 + 1];
                    float uv0 = au[s][nn][half * 2 + 0], uv1 = au[s][nn][half * 2 + 1];
                    float a0 = (gv0 / (1.f + expf(-gv0))) * uv0 * w;
                    float a1 = (gv1 / (1.f + expf(-gv1))) * uv1 * w;
                    uint32_t hi, lo;
                    split2(a0, a1, hi, lo);
                    int col = n0 + nc + nn * 8 + 2 * t4;
                    *(uint32_t*)&g_act_hi[slot][col] = hi;
                    *(uint32_t*)&g_act_lo[slot][col] = lo;
                }
            }
        }
    }
}

// ---------------- grouped GEMM B: out += act Wd^T (HMMA + atomics) ----------
__global__ __launch_bounds__(256) void down_mma_kernel(
    const float* __restrict__ wd, float* __restrict__ out)
{
    int e = blockIdx.z;
    int cnt = g_cnt[e];
    int m0 = blockIdx.y * 128;
    if (m0 >= cnt) return;
    int base = g_off[e];
    int n0 = blockIdx.x * 64;

    __shared__ __nv_bfloat16 AsH[128][KPAD], AsL[128][KPAD];
    __shared__ __nv_bfloat16 BsH[64][KPAD], BsL[64][KPAD];
    __shared__ int stok[128];

    int tid = threadIdx.x, wid = tid >> 5, lane = tid & 31;
    int g = lane >> 2, t4 = lane & 3;

    if (tid < 128) {
        int r = m0 + tid;
        stok[tid] = (r < cnt) ? g_slot_tok[base + r] : 0;
    }

    int lr = tid >> 1, lc = (tid & 1) * 16;
    int arow_idx = base + min(m0 + lr, cnt - 1);
    const __nv_bfloat16* ah = &g_act_hi[arow_idx][lc];
    const __nv_bfloat16* al = &g_act_lo[arow_idx][lc];
    bool doB = (tid < 128);
    int br = (tid & 127) >> 1, bc = (tid & 1) * 16;
    const float* wrow = wd + ((size_t)e * H_DIM + n0 + br) * I_DIM + bc;

    int mr = (wid & 3) * 32, nc = (wid >> 2) * 32;

    float dd[2][4][4] = {};

    uint2 ahv[4], alv[4];
    float4 bvv[4];
#pragma unroll
    for (int j = 0; j < 4; j++) {
        ahv[j] = *(const uint2*)(ah + 4 * j);
        alv[j] = *(const uint2*)(al + 4 * j);
        if (doB) bvv[j] = *(const float4*)(wrow + 4 * j);
    }

    for (int i = 0; i < I_DIM / KCH; i++) {
        __syncthreads();
#pragma unroll
        for (int j = 0; j < 4; j++) {
            *(uint2*)&AsH[lr][lc + 4 * j] = ahv[j];
            *(uint2*)&AsL[lr][lc + 4 * j] = alv[j];
        }
        if (doB) {
#pragma unroll
            for (int j = 0; j < 4; j++) {
                uint32_t h0, l0, h1, l1;
                split2(bvv[j].x, bvv[j].y, h0, l0);
                split2(bvv[j].z, bvv[j].w, h1, l1);
                *(uint2*)&BsH[br][bc + 4 * j] = make_uint2(h0, h1);
                *(uint2*)&BsL[br][bc + 4 * j] = make_uint2(l0, l1);
            }
        }
        __syncthreads();
        if (i + 1 < I_DIM / KCH) {
            int k0 = (i + 1) * KCH;
#pragma unroll
            for (int j = 0; j < 4; j++) {
                ahv[j] = *(const uint2*)(ah + k0 + 4 * j);
                alv[j] = *(const uint2*)(al + k0 + 4 * j);
                if (doB) bvv[j] = *(const float4*)(wrow + k0 + 4 * j);
            }
        }
#pragma unroll
        for (int kb = 0; kb < KCH; kb += 16) {
            uint32_t aH[2][4], aL[2][4], b0[4][2], b1[4][2];
#pragma unroll
            for (int s = 0; s < 2; s++) {
                int rb = mr + s * 16;
                aH[s][0] = *(const uint32_t*)&AsH[rb + g][kb + 2 * t4];
                aH[s][1] = *(const uint32_t*)&AsH[rb + g + 8][kb + 2 * t4];
                aH[s][2] = *(const uint32_t*)&AsH[rb + g][kb + 2 * t4 + 8];
                aH[s][3] = *(const uint32_t*)&AsH[rb + g + 8][kb + 2 * t4 + 8];
                aL[s][0] = *(const uint32_t*)&AsL[rb + g][kb + 2 * t4];
                aL[s][1] = *(const uint32_t*)&AsL[rb + g + 8][kb + 2 * t4];
                aL[s][2] = *(const uint32_t*)&AsL[rb + g][kb + 2 * t4 + 8];
                aL[s][3] = *(const uint32_t*)&AsL[rb + g + 8][kb + 2 * t4 + 8];
            }
#pragma unroll
            for (int nn = 0; nn < 4; nn++) {
                int n = nc + nn * 8 + g;
                b0[nn][0] = *(const uint32_t*)&BsH[n][kb + 2 * t4];
                b0[nn][1] = *(const uint32_t*)&BsH[n][kb + 2 * t4 + 8];
                b1[nn][0] = *(const uint32_t*)&BsL[n][kb + 2 * t4];
                b1[nn][1] = *(const uint32_t*)&BsL[n][kb + 2 * t4 + 8];
            }
#pragma unroll
            for (int s = 0; s < 2; s++)
#pragma unroll
                for (int nn = 0; nn < 4; nn++) {
                    mma16816(dd[s][nn], aH[s], b0[nn]);
                    mma16816(dd[s][nn], aH[s], b1[nn]);
                    mma16816(dd[s][nn], aL[s], b0[nn]);
                }
        }
    }

    // epilogue: atomic accumulate into out
#pragma unroll
    for (int s = 0; s < 2; s++) {
#pragma unroll
        for (int half = 0; half < 2; half++) {
            int rl = mr + s * 16 + g + half * 8;
            int r = m0 + rl;
            if (r < cnt) {
                int tok = stok[rl];
#pragma unroll
                for (int nn = 0; nn < 4; nn++) {
                    int col = n0 + nc + nn * 8 + 2 * t4;
                    float* orow = out + (size_t)tok * H_DIM + col;
                    atomicAdd(&orow[0], dd[s][nn][half * 2 + 0]);
                    atomicAdd(&orow[1], dd[s][nn][half * 2 + 1]);
                }
            }
        }
    }
}

// ---------------- launch ----------------
extern "C" void kernel_launch(void* const* d_in, const int* in_sizes, int n_in,
                              void* d_out, int out_size) {
    const float* hs    = (const float*)d_in[0];
    const float* gw    = (const float*)d_in[1];
    const float* wgate = (const float*)d_in[2];
    const float* wup   = (const float*)d_in[3];
    const float* wdown = (const float*)d_in[4];
    float* out = (float*)d_out;

    cudaMemsetAsync(d_out, 0, (size_t)out_size * sizeof(float));
    zero_meta_kernel<<<1, 32>>>();
    router_kernel<<<T_TOK, 128>>>(hs, gw);
    scan_kernel<<<1, 32>>>();
    scatter_kernel<<<T_TOK / 256, 256>>>();
    gateup_mma_kernel<<<dim3(I_DIM / 64, T_TOK / 128, E_NUM), 256>>>(hs, wgate, wup);
    down_mma_kernel  <<<dim3(H_DIM / 64, T_TOK / 128, E_NUM), 256>>>(wdown, out);
}

// round 6
// speedup vs baseline: 2.3675x; 1.5746x over previous
#include <cuda_runtime.h>
#include <cuda_bf16.h>
#include <math.h>
#include <stdint.h>

#define T_TOK 2048
#define H_DIM 2048
#define E_NUM 32
#define I_DIM 768
#define TOPK  8
#define NASSIGN (T_TOK * TOPK)

// ---------------- scratch ----------------
__device__ int   g_topk_id[T_TOK][TOPK];
__device__ float g_topk_w[T_TOK][TOPK];
__device__ int   g_cnt[E_NUM];
__device__ int   g_off[E_NUM + 1];
__device__ int   g_cur[E_NUM];
__device__ int   g_slot_tok[NASSIGN];
__device__ float g_slot_w[NASSIGN];
__device__ __nv_bfloat16 g_act_hi[NASSIGN][I_DIM];
__device__ __nv_bfloat16 g_act_lo[NASSIGN][I_DIM];

// ---------------- PTX helpers ----------------
__device__ __forceinline__ void mma16816(float* d, const uint32_t* a, const uint32_t* b) {
    asm volatile(
        "mma.sync.aligned.m16n8k16.row.col.f32.bf16.bf16.f32 "
        "{%0,%1,%2,%3}, {%4,%5,%6,%7}, {%8,%9}, {%0,%1,%2,%3};"
        : "+f"(d[0]), "+f"(d[1]), "+f"(d[2]), "+f"(d[3])
        : "r"(a[0]), "r"(a[1]), "r"(a[2]), "r"(a[3]), "r"(b[0]), "r"(b[1]));
}
#define LDMX4(r, addr) \
    asm volatile("ldmatrix.sync.aligned.m8n8.x4.shared.b16 {%0,%1,%2,%3}, [%4];" \
        : "=r"((r)[0]), "=r"((r)[1]), "=r"((r)[2]), "=r"((r)[3]) : "r"(addr))
#define CP16(dst, src) \
    asm volatile("cp.async.cg.shared.global [%0], [%1], 16;" :: "r"(dst), "l"(src))
#define CP_COMMIT() asm volatile("cp.async.commit_group;" ::: "memory")
#define CP_WAIT0()  asm volatile("cp.async.wait_group 0;" ::: "memory")

__device__ __forceinline__ uint32_t smem_u32(const void* p) {
    return (uint32_t)__cvta_generic_to_shared(p);
}
__device__ __forceinline__ void split2(float a, float b, uint32_t& hi, uint32_t& lo) {
    __nv_bfloat16 ha = __float2bfloat16(a), hb = __float2bfloat16(b);
    __nv_bfloat16 la = __float2bfloat16(a - __bfloat162float(ha));
    __nv_bfloat16 lb = __float2bfloat16(b - __bfloat162float(hb));
    __nv_bfloat162 ph; ph.x = ha; ph.y = hb; hi = *reinterpret_cast<uint32_t*>(&ph);
    __nv_bfloat162 pl; pl.x = la; pl.y = lb; lo = *reinterpret_cast<uint32_t*>(&pl);
}

// ---------------- meta / router / scan / scatter ----------------
__global__ void zero_meta_kernel() {
    int i = threadIdx.x;
    if (i < E_NUM) { g_cnt[i] = 0; g_cur[i] = 0; }
}

__global__ void router_kernel(const float* __restrict__ hs, const float* __restrict__ gw) {
    int t = blockIdx.x;
    __shared__ float part[128][E_NUM];
    __shared__ float sl[E_NUM];
    float acc[E_NUM];
#pragma unroll
    for (int e = 0; e < E_NUM; e++) acc[e] = 0.f;
    const float* hrow = hs + (size_t)t * H_DIM;
    for (int h = threadIdx.x; h < H_DIM; h += 128) {
        float x = hrow[h];
#pragma unroll
        for (int e = 0; e < E_NUM; e++) acc[e] += x * gw[e * H_DIM + h];
    }
#pragma unroll
    for (int e = 0; e < E_NUM; e++) part[threadIdx.x][e] = acc[e];
    __syncthreads();
    if (threadIdx.x < E_NUM) {
        float s = 0.f;
        for (int i = 0; i < 128; i++) s += part[i][threadIdx.x];
        sl[threadIdx.x] = s;
    }
    __syncthreads();
    if (threadIdx.x == 0) {
        unsigned mask = 0;
        int ids[TOPK]; float lv[TOPK];
        for (int k = 0; k < TOPK; k++) {
            float best = -3.4e38f; int bi = 0;
            for (int e = 0; e < E_NUM; e++)
                if (!((mask >> e) & 1u) && sl[e] > best) { best = sl[e]; bi = e; }
            mask |= (1u << bi); ids[k] = bi; lv[k] = best;
        }
        float mx = lv[0], s = 0.f, w[TOPK];
        for (int k = 0; k < TOPK; k++) { w[k] = expf(lv[k] - mx); s += w[k]; }
        float inv = 1.f / s;
        for (int k = 0; k < TOPK; k++) {
            g_topk_id[t][k] = ids[k];
            g_topk_w[t][k]  = w[k] * inv;
            atomicAdd(&g_cnt[ids[k]], 1);
        }
    }
}

__global__ void scan_kernel() {
    if (threadIdx.x == 0) {
        int s = 0;
        g_off[0] = 0;
        for (int e = 0; e < E_NUM; e++) { s += g_cnt[e]; g_off[e + 1] = s; }
    }
}

__global__ void scatter_kernel() {
    int t = blockIdx.x * blockDim.x + threadIdx.x;
    if (t >= T_TOK) return;
#pragma unroll
    for (int k = 0; k < TOPK; k++) {
        int e = g_topk_id[t][k];
        float w = g_topk_w[t][k];
        int p = atomicAdd(&g_cur[e], 1);
        int s = g_off[e] + p;
        g_slot_tok[s] = t;
        g_slot_w[s]  = w;
    }
}

// ======================= gate-up GEMM (KCH=16, KPAD=24) =======================
// stage layout (bytes): A_H 0 (6144) | A_L 6144 | BG_H 12288 (3072) | BG_L 15360
//                       | BU_H 18432 | BU_L 21504 ; STAGE = 24576
#define GU_STAGE 24576
#define GU_META  49152            // stok(512) + swt(512)
#define GU_SMEM  (GU_META + 1024)

__global__ __launch_bounds__(256, 2) void gateup_mma_kernel(
    const float* __restrict__ hs,
    const float* __restrict__ wg,
    const float* __restrict__ wu)
{
    int e = blockIdx.z;
    int cnt = g_cnt[e];
    int m0 = blockIdx.y * 128;
    if (m0 >= cnt) return;
    int base = g_off[e];
    int n0 = blockIdx.x * 64;

    extern __shared__ char smem[];
    uint32_t sb = smem_u32(smem);
    int tid = threadIdx.x, wid = tid >> 5, lane = tid & 31;
    int g = lane >> 2, t4 = lane & 3;

    int*   stok = (int*)(smem + GU_META);
    float* swt  = (float*)(smem + GU_META + 512);
    if (tid < 128) {
        int r = m0 + tid;
        int rc = (r < cnt) ? r : (cnt - 1);
        stok[tid] = g_slot_tok[base + rc];
        swt[tid]  = (r < cnt) ? g_slot_w[base + rc] : 0.f;
    }
    __syncthreads();

    // loaders: A rows 0..127 (2 thr/row, 8 fp32 each); B rows 0..63 (gate tid<128, up >=128)
    int lr = tid >> 1, lc = (tid & 1) * 8;
    const float* arow = hs + (size_t)stok[lr] * H_DIM + lc;
    int bt = tid & 127, br = bt >> 1, bc = (bt & 1) * 8;
    const float* wrow = ((tid >= 128) ? wu : wg) + ((size_t)e * I_DIM + n0 + br) * H_DIM + bc;
    uint32_t aoff = (uint32_t)(lr * 48 + lc * 2);
    uint32_t boff = (uint32_t)((tid >= 128 ? 18432 : 12288) + br * 48 + bc * 2);

    // fragment addressing (ldmatrix)
    int quad = lane >> 3, r8 = lane & 7;
    int aRow = (quad & 1) * 8 + r8, aCol = (quad >> 1) * 8;
    int bRow = (quad >> 1) * 8 + r8, bCol = (quad & 1) * 8;
    int mr = (wid & 3) * 32, nc = (wid >> 2) * 32;
    uint32_t aBase = sb + (uint32_t)((mr + aRow) * 48 + aCol * 2);
    uint32_t bBase = sb + 12288u + (uint32_t)((nc + bRow) * 48 + bCol * 2);

    float ag[2][4][4] = {}, au[2][4][4] = {};
    float4 av[2], bv[2];
#pragma unroll
    for (int j = 0; j < 2; j++) {
        av[j] = *(const float4*)(arow + 4 * j);
        bv[j] = *(const float4*)(wrow + 4 * j);
    }
    // store chunk 0 -> stage 0
#pragma unroll
    for (int j = 0; j < 2; j++) {
        uint32_t h0, l0, h1, l1;
        split2(av[j].x, av[j].y, h0, l0); split2(av[j].z, av[j].w, h1, l1);
        *(uint2*)(smem + aoff + 8 * j) = make_uint2(h0, h1);
        *(uint2*)(smem + 6144 + aoff + 8 * j) = make_uint2(l0, l1);
        split2(bv[j].x, bv[j].y, h0, l0); split2(bv[j].z, bv[j].w, h1, l1);
        *(uint2*)(smem + boff + 8 * j) = make_uint2(h0, h1);
        *(uint2*)(smem + 3072 + boff + 8 * j) = make_uint2(l0, l1);
    }
    __syncthreads();

    const int NCH = H_DIM / 16;   // 128
    for (int i = 0; i < NCH; i++) {
        int stg = i & 1;
        if (i + 1 < NCH) {
            int k0 = (i + 1) * 16;
#pragma unroll
            for (int j = 0; j < 2; j++) {
                av[j] = *(const float4*)(arow + k0 + 4 * j);
                bv[j] = *(const float4*)(wrow + k0 + 4 * j);
            }
        }
        uint32_t aA = aBase + stg * GU_STAGE;
        uint32_t bA = bBase + stg * GU_STAGE;
        uint32_t aH[2][4], aL[2][4], bh[4], bl[4];
        LDMX4(aH[0], aA);        LDMX4(aH[1], aA + 768);
        LDMX4(aL[0], aA + 6144); LDMX4(aL[1], aA + 6144 + 768);
#pragma unroll
        for (int p = 0; p < 2; p++) {       // gate
            LDMX4(bh, bA + p * 768);
            LDMX4(bl, bA + 3072 + p * 768);
#pragma unroll
            for (int s = 0; s < 2; s++) {
                mma16816(ag[s][2 * p + 0], aH[s], bh);
                mma16816(ag[s][2 * p + 0], aH[s], bl);
                mma16816(ag[s][2 * p + 0], aL[s], bh);
                mma16816(ag[s][2 * p + 1], aH[s], bh + 2);
                mma16816(ag[s][2 * p + 1], aH[s], bl + 2);
                mma16816(ag[s][2 * p + 1], aL[s], bh + 2);
            }
        }
#pragma unroll
        for (int p = 0; p < 2; p++) {       // up
            LDMX4(bh, bA + 6144 + p * 768);
            LDMX4(bl, bA + 6144 + 3072 + p * 768);
#pragma unroll
            for (int s = 0; s < 2; s++) {
                mma16816(au[s][2 * p + 0], aH[s], bh);
                mma16816(au[s][2 * p + 0], aH[s], bl);
                mma16816(au[s][2 * p + 0], aL[s], bh);
                mma16816(au[s][2 * p + 1], aH[s], bh + 2);
                mma16816(au[s][2 * p + 1], aH[s], bl + 2);
                mma16816(au[s][2 * p + 1], aL[s], bh + 2);
            }
        }
        if (i + 1 < NCH) {
            uint32_t so = ((i + 1) & 1) * GU_STAGE;
#pragma unroll
            for (int j = 0; j < 2; j++) {
                uint32_t h0, l0, h1, l1;
                split2(av[j].x, av[j].y, h0, l0); split2(av[j].z, av[j].w, h1, l1);
                *(uint2*)(smem + so + aoff + 8 * j) = make_uint2(h0, h1);
                *(uint2*)(smem + so + 6144 + aoff + 8 * j) = make_uint2(l0, l1);
                split2(bv[j].x, bv[j].y, h0, l0); split2(bv[j].z, bv[j].w, h1, l1);
                *(uint2*)(smem + so + boff + 8 * j) = make_uint2(h0, h1);
                *(uint2*)(smem + so + 3072 + boff + 8 * j) = make_uint2(l0, l1);
            }
        }
        __syncthreads();
    }

    // epilogue: silu(g)*u*route_w -> bf16 hi/lo scratch
#pragma unroll
    for (int s = 0; s < 2; s++) {
#pragma unroll
        for (int half = 0; half < 2; half++) {
            int rl = mr + s * 16 + g + half * 8;
            int r = m0 + rl;
            if (r < cnt) {
                float w = swt[rl];
                size_t slot = (size_t)(base + r);
#pragma unroll
                for (int nn = 0; nn < 4; nn++) {
                    float gv0 = ag[s][nn][half * 2 + 0], gv1 = ag[s][nn][half * 2 + 1];
                    float uv0 = au[s][nn][half * 2 + 0], uv1 = au[s][nn][half * 2 + 1];
                    float a0 = (gv0 / (1.f + expf(-gv0))) * uv0 * w;
                    float a1 = (gv1 / (1.f + expf(-gv1))) * uv1 * w;
                    uint32_t hi, lo;
                    split2(a0, a1, hi, lo);
                    int col = n0 + nc + nn * 8 + 2 * t4;
                    *(uint32_t*)&g_act_hi[slot][col] = hi;
                    *(uint32_t*)&g_act_lo[slot][col] = lo;
                }
            }
        }
    }
}

// ======================= down GEMM (KCH=32, KPAD=40) =========================
// stage layout: A_H 0 (10240) | A_L 10240 | B_H 20480 (5120) | B_L 25600 ; STAGE 30720
#define DN_STAGE 30720
#define DN_META  61440
#define DN_SMEM  (DN_META + 512)

__global__ __launch_bounds__(256, 2) void down_mma_kernel(
    const float* __restrict__ wd, float* __restrict__ out)
{
    int e = blockIdx.z;
    int cnt = g_cnt[e];
    int m0 = blockIdx.y * 128;
    if (m0 >= cnt) return;
    int base = g_off[e];
    int n0 = blockIdx.x * 64;

    extern __shared__ char smem[];
    uint32_t sb = smem_u32(smem);
    int tid = threadIdx.x, wid = tid >> 5, lane = tid & 31;
    int g = lane >> 2, t4 = lane & 3;

    int* stok = (int*)(smem + DN_META);
    if (tid < 128) {
        int r = m0 + tid;
        stok[tid] = (r < cnt) ? g_slot_tok[base + r] : 0;
    }

    // A via cp.async: 2 thr/row, 16 halves each of hi and lo
    int arw = tid >> 1, alc = (tid & 1) * 16;
    int arow_idx = base + min(m0 + arw, cnt - 1);
    const __nv_bfloat16* ah = &g_act_hi[arow_idx][alc];
    const __nv_bfloat16* al = &g_act_lo[arow_idx][alc];
    uint32_t aDst = sb + (uint32_t)(arw * 80 + alc * 2);
    // B loader: 4 thr/row, 8 fp32 each
    int br = tid >> 2, bc = (tid & 3) * 8;
    const float* wrow = wd + ((size_t)e * H_DIM + n0 + br) * I_DIM + bc;
    uint32_t boff = (uint32_t)(20480 + br * 80 + bc * 2);

    int quad = lane >> 3, r8 = lane & 7;
    int aRow = (quad & 1) * 8 + r8, aCol = (quad >> 1) * 8;
    int bRow = (quad >> 1) * 8 + r8, bCol = (quad & 1) * 8;
    int mr = (wid & 3) * 32, nc = (wid >> 2) * 32;
    uint32_t aBase = sb + (uint32_t)((mr + aRow) * 80 + aCol * 2);
    uint32_t bBase = sb + 20480u + (uint32_t)((nc + bRow) * 80 + bCol * 2);

    float dd[2][4][4] = {};
    float4 bv[2];

    // prologue: chunk 0
    CP16(aDst,         (const char*)ah);
    CP16(aDst + 16,    (const char*)(ah + 8));
    CP16(aDst + 10240, (const char*)al);
    CP16(aDst + 10240 + 16, (const char*)(al + 8));
    CP_COMMIT();
#pragma unroll
    for (int j = 0; j < 2; j++) bv[j] = *(const float4*)(wrow + 4 * j);
#pragma unroll
    for (int j = 0; j < 2; j++) {
        uint32_t h0, l0, h1, l1;
        split2(bv[j].x, bv[j].y, h0, l0); split2(bv[j].z, bv[j].w, h1, l1);
        *(uint2*)(smem + boff + 8 * j) = make_uint2(h0, h1);
        *(uint2*)(smem + 5120 + boff + 8 * j) = make_uint2(l0, l1);
    }
    CP_WAIT0();
    __syncthreads();

    const int NCH = I_DIM / 32;   // 24
    for (int i = 0; i < NCH; i++) {
        int stg = i & 1;
        if (i + 1 < NCH) {
            int k0 = (i + 1) * 32;
            uint32_t so = ((i + 1) & 1) * DN_STAGE;
            CP16(aDst + so,              (const char*)(ah + k0));
            CP16(aDst + so + 16,         (const char*)(ah + k0 + 8));
            CP16(aDst + so + 10240,      (const char*)(al + k0));
            CP16(aDst + so + 10240 + 16, (const char*)(al + k0 + 8));
            CP_COMMIT();
#pragma unroll
            for (int j = 0; j < 2; j++) bv[j] = *(const float4*)(wrow + k0 + 4 * j);
        }
#pragma unroll
        for (int kb = 0; kb < 32; kb += 16) {
            uint32_t aA = aBase + stg * DN_STAGE + kb * 2;
            uint32_t bA = bBase + stg * DN_STAGE + kb * 2;
            uint32_t aH[2][4], aL[2][4], bh[4], bl[4];
            LDMX4(aH[0], aA);         LDMX4(aH[1], aA + 1280);
            LDMX4(aL[0], aA + 10240); LDMX4(aL[1], aA + 10240 + 1280);
#pragma unroll
            for (int p = 0; p < 2; p++) {
                LDMX4(bh, bA + p * 1280);
                LDMX4(bl, bA + 5120 + p * 1280);
#pragma unroll
                for (int s = 0; s < 2; s++) {
                    mma16816(dd[s][2 * p + 0], aH[s], bh);
                    mma16816(dd[s][2 * p + 0], aH[s], bl);
                    mma16816(dd[s][2 * p + 0], aL[s], bh);
                    mma16816(dd[s][2 * p + 1], aH[s], bh + 2);
                    mma16816(dd[s][2 * p + 1], aH[s], bl + 2);
                    mma16816(dd[s][2 * p + 1], aL[s], bh + 2);
                }
            }
        }
        if (i + 1 < NCH) {
            uint32_t so = ((i + 1) & 1) * DN_STAGE;
#pragma unroll
            for (int j = 0; j < 2; j++) {
                uint32_t h0, l0, h1, l1;
                split2(bv[j].x, bv[j].y, h0, l0); split2(bv[j].z, bv[j].w, h1, l1);
                *(uint2*)(smem + so + boff + 8 * j) = make_uint2(h0, h1);
                *(uint2*)(smem + so + 5120 + boff + 8 * j) = make_uint2(l0, l1);
            }
        }
        CP_WAIT0();
        __syncthreads();
    }

    // epilogue: atomic accumulate
#pragma unroll
    for (int s = 0; s < 2; s++) {
#pragma unroll
        for (int half = 0; half < 2; half++) {
            int rl = mr + s * 16 + g + half * 8;
            int r = m0 + rl;
            if (r < cnt) {
                int tok = stok[rl];
#pragma unroll
                for (int nn = 0; nn < 4; nn++) {
                    int col = n0 + nc + nn * 8 + 2 * t4;
                    float* orow = out + (size_t)tok * H_DIM + col;
                    atomicAdd(&orow[0], dd[s][nn][half * 2 + 0]);
                    atomicAdd(&orow[1], dd[s][nn][half * 2 + 1]);
                }
            }
        }
    }
}

// ---------------- launch ----------------
extern "C" void kernel_launch(void* const* d_in, const int* in_sizes, int n_in,
                              void* d_out, int out_size) {
    const float* hs    = (const float*)d_in[0];
    const float* gw    = (const float*)d_in[1];
    const float* wgate = (const float*)d_in[2];
    const float* wup   = (const float*)d_in[3];
    const float* wdown = (const float*)d_in[4];
    float* out = (float*)d_out;

    cudaFuncSetAttribute(gateup_mma_kernel, cudaFuncAttributeMaxDynamicSharedMemorySize, GU_SMEM);
    cudaFuncSetAttribute(down_mma_kernel,   cudaFuncAttributeMaxDynamicSharedMemorySize, DN_SMEM);

    cudaMemsetAsync(d_out, 0, (size_t)out_size * sizeof(float));
    zero_meta_kernel<<<1, 32>>>();
    router_kernel<<<T_TOK, 128>>>(hs, gw);
    scan_kernel<<<1, 32>>>();
    scatter_kernel<<<T_TOK / 256, 256>>>();
    gateup_mma_kernel<<<dim3(I_DIM / 64, T_TOK / 128, E_NUM), 256, GU_SMEM>>>(hs, wgate, wup);
    down_mma_kernel  <<<dim3(H_DIM / 64, T_TOK / 128, E_NUM), 256, DN_SMEM>>>(wdown, out);
}

// round 8
// speedup vs baseline: 2.7749x; 1.1721x over previous
#include <cuda_runtime.h>
#include <cuda_fp16.h>
#include <math.h>
#include <stdint.h>

#define T_TOK 2048
#define H_DIM 2048
#define E_NUM 32
#define I_DIM 768
#define TOPK  8
#define NASSIGN (T_TOK * TOPK)
#define NW ((size_t)E_NUM * I_DIM * H_DIM)   // 50331648 per weight tensor

// ---------------- scratch ----------------
__device__ int   g_topk_id[T_TOK][TOPK];
__device__ float g_topk_w[T_TOK][TOPK];
__device__ int   g_cnt[E_NUM];
__device__ int   g_off[E_NUM + 1];
__device__ int   g_slot_tok[NASSIGN];
__device__ float g_slot_w[NASSIGN];
__device__ __half g_wg_h[NW];                   // 100.7 MB
__device__ __half g_wu_h[NW];
__device__ __half g_wd_h[NW];
__device__ __half g_hs_hi[(size_t)T_TOK * H_DIM];
__device__ __half g_hs_lo[(size_t)T_TOK * H_DIM];
__device__ __half g_act_hi[NASSIGN][I_DIM];     // 25 MB
__device__ __half g_act_lo[NASSIGN][I_DIM];

// ---------------- PTX helpers ----------------
__device__ __forceinline__ void mma16816(float* d, const uint32_t* a, const uint32_t* b) {
    asm volatile(
        "mma.sync.aligned.m16n8k16.row.col.f32.f16.f16.f32 "
        "{%0,%1,%2,%3}, {%4,%5,%6,%7}, {%8,%9}, {%0,%1,%2,%3};"
        : "+f"(d[0]), "+f"(d[1]), "+f"(d[2]), "+f"(d[3])
        : "r"(a[0]), "r"(a[1]), "r"(a[2]), "r"(a[3]), "r"(b[0]), "r"(b[1]));
}
#define LDMX4(r, addr) \
    asm volatile("ldmatrix.sync.aligned.m8n8.x4.shared.b16 {%0,%1,%2,%3}, [%4];" \
        : "=r"((r)[0]), "=r"((r)[1]), "=r"((r)[2]), "=r"((r)[3]) : "r"(addr))
#define CP16(dst, src) \
    asm volatile("cp.async.cg.shared.global [%0], [%1], 16;" :: "r"(dst), "l"(src))
#define CP_COMMIT() asm volatile("cp.async.commit_group;" ::: "memory")
#define CP_WAIT1()  asm volatile("cp.async.wait_group 1;" ::: "memory")
#define CP_WAIT0()  asm volatile("cp.async.wait_group 0;" ::: "memory")

__device__ __forceinline__ uint32_t smem_u32(const void* p) {
    return (uint32_t)__cvta_generic_to_shared(p);
}
// fp32 pair -> packed fp16x2 hi + fp16x2 lo (residual)
__device__ __forceinline__ void split2h(float a, float b, uint32_t& hi, uint32_t& lo) {
    __half ha = __float2half_rn(a), hb = __float2half_rn(b);
    __half la = __float2half_rn(a - __half2float(ha));
    __half lb = __float2half_rn(b - __half2float(hb));
    __half2 ph; ph.x = ha; ph.y = hb; hi = *reinterpret_cast<uint32_t*>(&ph);
    __half2 pl; pl.x = la; pl.y = lb; lo = *reinterpret_cast<uint32_t*>(&pl);
}

// ---------------- weight convert: fp32 -> single fp16 ----------------
__global__ void conv_w_kernel(const float* __restrict__ wg,
                              const float* __restrict__ wu,
                              const float* __restrict__ wd) {
    size_t total8 = (3 * NW) / 8;
    for (size_t i = (size_t)blockIdx.x * blockDim.x + threadIdx.x; i < total8;
         i += (size_t)gridDim.x * blockDim.x) {
        size_t e8 = i * 8;
        const float* src; __half* dst;
        if (e8 < NW)          { src = wg + e8;          dst = g_wg_h + e8; }
        else if (e8 < 2 * NW) { src = wu + (e8 - NW);   dst = g_wu_h + (e8 - NW); }
        else                  { src = wd + (e8 - 2*NW); dst = g_wd_h + (e8 - 2*NW); }
        float4 v0 = *(const float4*)src;
        float4 v1 = *(const float4*)(src + 4);
        __half2 h0 = __floats2half2_rn(v0.x, v0.y);
        __half2 h1 = __floats2half2_rn(v0.z, v0.w);
        __half2 h2 = __floats2half2_rn(v1.x, v1.y);
        __half2 h3 = __floats2half2_rn(v1.z, v1.w);
        uint4 o;
        o.x = *(uint32_t*)&h0; o.y = *(uint32_t*)&h1;
        o.z = *(uint32_t*)&h2; o.w = *(uint32_t*)&h3;
        *(uint4*)dst = o;
    }
}

// ---------------- hidden convert: fp32 -> fp16 hi/lo (+ zero g_cnt) ---------
__global__ void conv_hs_kernel(const float* __restrict__ hs) {
    if (blockIdx.x == 0 && threadIdx.x < E_NUM) g_cnt[threadIdx.x] = 0;
    size_t total4 = (size_t)T_TOK * H_DIM / 4;
    for (size_t i = (size_t)blockIdx.x * blockDim.x + threadIdx.x; i < total4;
         i += (size_t)gridDim.x * blockDim.x) {
        float4 v = *(const float4*)(hs + i * 4);
        uint32_t h0, l0, h1, l1;
        split2h(v.x, v.y, h0, l0);
        split2h(v.z, v.w, h1, l1);
        *(uint2*)&g_hs_hi[i * 4] = make_uint2(h0, h1);
        *(uint2*)&g_hs_lo[i * 4] = make_uint2(l0, l1);
    }
}

// ---------------- router (unchanged math) ----------------
__global__ void router_kernel(const float* __restrict__ hs, const float* __restrict__ gw) {
    int t = blockIdx.x;
    __shared__ float part[128][E_NUM];
    __shared__ float sl[E_NUM];
    float acc[E_NUM];
#pragma unroll
    for (int e = 0; e < E_NUM; e++) acc[e] = 0.f;
    const float* hrow = hs + (size_t)t * H_DIM;
    for (int h = threadIdx.x; h < H_DIM; h += 128) {
        float x = hrow[h];
#pragma unroll
        for (int e = 0; e < E_NUM; e++) acc[e] += x * gw[e * H_DIM + h];
    }
#pragma unroll
    for (int e = 0; e < E_NUM; e++) part[threadIdx.x][e] = acc[e];
    __syncthreads();
    if (threadIdx.x < E_NUM) {
        float s = 0.f;
        for (int i = 0; i < 128; i++) s += part[i][threadIdx.x];
        sl[threadIdx.x] = s;
    }
    __syncthreads();
    if (threadIdx.x == 0) {
        unsigned mask = 0;
        int ids[TOPK]; float lv[TOPK];
        for (int k = 0; k < TOPK; k++) {
            float best = -3.4e38f; int bi = 0;
            for (int e = 0; e < E_NUM; e++)
                if (!((mask >> e) & 1u) && sl[e] > best) { best = sl[e]; bi = e; }
            mask |= (1u << bi); ids[k] = bi; lv[k] = best;
        }
        float mx = lv[0], s = 0.f, w[TOPK];
        for (int k = 0; k < TOPK; k++) { w[k] = expf(lv[k] - mx); s += w[k]; }
        float inv = 1.f / s;
        for (int k = 0; k < TOPK; k++) {
            g_topk_id[t][k] = ids[k];
            g_topk_w[t][k]  = w[k] * inv;
            atomicAdd(&g_cnt[ids[k]], 1);
        }
    }
}

// ---------------- fused scan + scatter (single block) ----------------
__global__ void dispatch_kernel() {
    __shared__ int soff[E_NUM];
    __shared__ int scur[E_NUM];
    int tid = threadIdx.x;
    if (tid < E_NUM) scur[tid] = 0;
    if (tid == 0) {
        int s = 0;
        for (int e = 0; e < E_NUM; e++) {
            g_off[e] = s; soff[e] = s; s += g_cnt[e];
        }
        g_off[E_NUM] = s;
    }
    __syncthreads();
    for (int t = tid; t < T_TOK; t += 256) {
#pragma unroll
        for (int k = 0; k < TOPK; k++) {
            int e = g_topk_id[t][k];
            int p = atomicAdd(&scur[e], 1);
            int s = soff[e] + p;
            g_slot_tok[s] = t;
            g_slot_w[s]  = g_topk_w[t][k];
        }
    }
}

// ======================= gate-up GEMM: fp16 2-term, 3-stage =================
// stage (bytes): A_H 0 (128x80=10240) | A_L 10240 | B_G 20480 (64x80=5120) | B_U 25600
#define GU_STAGE 30720
#define GU_META  (3 * GU_STAGE)          // stok 512 + swt 512
#define GU_SMEM  (GU_META + 1024)
#define GU_NCH   (H_DIM / 32)            // 64

__global__ __launch_bounds__(256, 2) void gateup_mma_kernel() {
    int e = blockIdx.z;
    int cnt = g_cnt[e];
    int m0 = blockIdx.y * 128;
    if (m0 >= cnt) return;
    int base = g_off[e];
    int n0 = blockIdx.x * 64;

    extern __shared__ char smem[];
    uint32_t sb = smem_u32(smem);
    int tid = threadIdx.x, wid = tid >> 5, lane = tid & 31;
    int g = lane >> 2, t4 = lane & 3;

    int*   stok = (int*)(smem + GU_META);
    float* swt  = (float*)(smem + GU_META + 512);
    if (tid < 128) {
        int r = m0 + tid;
        int rc = (r < cnt) ? r : (cnt - 1);
        stok[tid] = g_slot_tok[base + rc];
        swt[tid]  = (r < cnt) ? g_slot_w[base + rc] : 0.f;
    }
    __syncthreads();

    // cp.async source/dest mapping
    int lr = tid >> 1, asel = tid & 1;                 // A: 2 thr/row, 32B each
    const __half* ah_src = g_hs_hi + (size_t)stok[lr] * H_DIM + asel * 16;
    const __half* al_src = g_hs_lo + (size_t)stok[lr] * H_DIM + asel * 16;
    uint32_t aDst = sb + (uint32_t)(lr * 80 + asel * 32);
    int bt = tid & 127, br = bt >> 1, bsel = bt & 1;   // B: 2 thr/row, 32B each
    const __half* b_src = ((tid >= 128) ? g_wu_h : g_wg_h)
                          + ((size_t)e * I_DIM + n0 + br) * H_DIM + bsel * 16;
    uint32_t bDst = sb + 20480u + (tid >= 128 ? 5120u : 0u) + (uint32_t)(br * 80 + bsel * 32);

    // ldmatrix fragment addressing
    int quad = lane >> 3, r8 = lane & 7;
    int aRow = (quad & 1) * 8 + r8, aCol = (quad >> 1) * 8;
    int bRow = (quad >> 1) * 8 + r8, bCol = (quad & 1) * 8;
    int mr = (wid & 3) * 32, nc = (wid >> 2) * 32;
    uint32_t aBase = sb + (uint32_t)((mr + aRow) * 80 + aCol * 2);
    uint32_t bBase = sb + 20480u + (uint32_t)((nc + bRow) * 80 + bCol * 2);

    float ag[2][4][4] = {}, au[2][4][4] = {};

#define GU_ISSUE(i) do { \
    uint32_t so = (uint32_t)((i) % 3) * GU_STAGE; \
    int k0 = (i) * 32; \
    CP16(aDst + so,              (const char*)(ah_src + k0)); \
    CP16(aDst + so + 16,         (const char*)(ah_src + k0 + 8)); \
    CP16(aDst + so + 10240,      (const char*)(al_src + k0)); \
    CP16(aDst + so + 10240 + 16, (const char*)(al_src + k0 + 8)); \
    CP16(bDst + so,              (const char*)(b_src + k0)); \
    CP16(bDst + so + 16,         (const char*)(b_src + k0 + 8)); \
    CP_COMMIT(); \
} while (0)

    GU_ISSUE(0);
    GU_ISSUE(1);

    for (int i = 0; i < GU_NCH; i++) {
        if (i + 1 < GU_NCH) CP_WAIT1(); else CP_WAIT0();
        __syncthreads();
        if (i + 2 < GU_NCH) GU_ISSUE(i + 2);
        uint32_t so = (uint32_t)(i % 3) * GU_STAGE;
#pragma unroll
        for (int kb = 0; kb < 2; kb++) {
            uint32_t aH[2][4], aL[2][4];
            uint32_t aA = aBase + so + kb * 32;
            LDMX4(aH[0], aA);                LDMX4(aH[1], aA + 16 * 80);
            LDMX4(aL[0], aA + 10240);        LDMX4(aL[1], aA + 10240 + 16 * 80);
#pragma unroll
            for (int p = 0; p < 2; p++) {
                uint32_t bg[4], bu[4];
                uint32_t bA = bBase + so + p * 16 * 80 + kb * 32;
                LDMX4(bg, bA);
                LDMX4(bu, bA + 5120);
#pragma unroll
                for (int s = 0; s < 2; s++) {
                    mma16816(ag[s][2 * p + 0], aH[s], bg);
                    mma16816(ag[s][2 * p + 1], aH[s], bg + 2);
                    mma16816(au[s][2 * p + 0], aH[s], bu);
                    mma16816(au[s][2 * p + 1], aH[s], bu + 2);
                }
#pragma unroll
                for (int s = 0; s < 2; s++) {
                    mma16816(ag[s][2 * p + 0], aL[s], bg);
                    mma16816(ag[s][2 * p + 1], aL[s], bg + 2);
                    mma16816(au[s][2 * p + 0], aL[s], bu);
                    mma16816(au[s][2 * p + 1], aL[s], bu + 2);
                }
            }
        }
        __syncthreads();
    }

    // epilogue: silu(g)*u*route_w -> fp16 hi/lo scratch
#pragma unroll
    for (int s = 0; s < 2; s++) {
#pragma unroll
        for (int half = 0; half < 2; half++) {
            int rl = mr + s * 16 + g + half * 8;
            int r = m0 + rl;
            if (r < cnt) {
                float w = swt[rl];
                size_t slot = (size_t)(base + r);
#pragma unroll
                for (int nn = 0; nn < 4; nn++) {
                    float gv0 = ag[s][nn][half * 2 + 0], gv1 = ag[s][nn][half * 2 + 1];
                    float uv0 = au[s][nn][half * 2 + 0], uv1 = au[s][nn][half * 2 + 1];
                    float a0 = (gv0 / (1.f + expf(-gv0))) * uv0 * w;
                    float a1 = (gv1 / (1.f + expf(-gv1))) * uv1 * w;
                    uint32_t hi, lo;
                    split2h(a0, a1, hi, lo);
                    int col = n0 + nc + nn * 8 + 2 * t4;
                    *(uint32_t*)&g_act_hi[slot][col] = hi;
                    *(uint32_t*)&g_act_lo[slot][col] = lo;
                }
            }
        }
    }
#undef GU_ISSUE
}

// ======================= down GEMM: fp16 2-term, 3-stage ====================
// stage: A_H 0 (10240) | A_L 10240 | B 20480 (5120) ; STAGE 25600
#define DN_STAGE 25600
#define DN_META  (3 * DN_STAGE)
#define DN_SMEM  (DN_META + 512)
#define DN_NCH   (I_DIM / 32)            // 24

__global__ __launch_bounds__(256, 2) void down_mma_kernel(float* __restrict__ out) {
    int e = blockIdx.z;
    int cnt = g_cnt[e];
    int m0 = blockIdx.y * 128;
    if (m0 >= cnt) return;
    int base = g_off[e];
    int n0 = blockIdx.x * 64;

    extern __shared__ char smem[];
    uint32_t sb = smem_u32(smem);
    int tid = threadIdx.x, wid = tid >> 5, lane = tid & 31;
    int g = lane >> 2, t4 = lane & 3;

    int* stok = (int*)(smem + DN_META);
    if (tid < 128) {
        int r = m0 + tid;
        stok[tid] = (r < cnt) ? g_slot_tok[base + r] : 0;
    }
    __syncthreads();

    int lr = tid >> 1, asel = tid & 1;
    int arow_idx = base + min(m0 + lr, cnt - 1);
    const __half* ah_src = &g_act_hi[arow_idx][asel * 16];
    const __half* al_src = &g_act_lo[arow_idx][asel * 16];
    uint32_t aDst = sb + (uint32_t)(lr * 80 + asel * 32);
    int br = tid >> 2, bsel = tid & 3;                  // B: 4 thr/row, 16B each
    const __half* b_src = g_wd_h + ((size_t)e * H_DIM + n0 + br) * I_DIM + bsel * 8;
    uint32_t bDst = sb + 20480u + (uint32_t)(br * 80 + bsel * 16);

    int quad = lane >> 3, r8 = lane & 7;
    int aRow = (quad & 1) * 8 + r8, aCol = (quad >> 1) * 8;
    int bRow = (quad >> 1) * 8 + r8, bCol = (quad & 1) * 8;
    int mr = (wid & 3) * 32, nc = (wid >> 2) * 32;
    uint32_t aBase = sb + (uint32_t)((mr + aRow) * 80 + aCol * 2);
    uint32_t bBase = sb + 20480u + (uint32_t)((nc + bRow) * 80 + bCol * 2);

    float dd[2][4][4] = {};

#define DN_ISSUE(i) do { \
    uint32_t so = (uint32_t)((i) % 3) * DN_STAGE; \
    int k0 = (i) * 32; \
    CP16(aDst + so,              (const char*)(ah_src + k0)); \
    CP16(aDst + so + 16,         (const char*)(ah_src + k0 + 8)); \
    CP16(aDst + so + 10240,      (const char*)(al_src + k0)); \
    CP16(aDst + so + 10240 + 16, (const char*)(al_src + k0 + 8)); \
    CP16(bDst + so,              (const char*)(b_src + k0)); \
    CP_COMMIT(); \
} while (0)

    DN_ISSUE(0);
    DN_ISSUE(1);

    for (int i = 0; i < DN_NCH; i++) {
        if (i + 1 < DN_NCH) CP_WAIT1(); else CP_WAIT0();
        __syncthreads();
        if (i + 2 < DN_NCH) DN_ISSUE(i + 2);
        uint32_t so = (uint32_t)(i % 3) * DN_STAGE;
#pragma unroll
        for (int kb = 0; kb < 2; kb++) {
            uint32_t aH[2][4], aL[2][4];
            uint32_t aA = aBase + so + kb * 32;
            LDMX4(aH[0], aA);         LDMX4(aH[1], aA + 16 * 80);
            LDMX4(aL[0], aA + 10240); LDMX4(aL[1], aA + 10240 + 16 * 80);
#pragma unroll
            for (int p = 0; p < 2; p++) {
                uint32_t bh[4];
                uint32_t bA = bBase + so + p * 16 * 80 + kb * 32;
                LDMX4(bh, bA);
#pragma unroll
                for (int s = 0; s < 2; s++) {
                    mma16816(dd[s][2 * p + 0], aH[s], bh);
                    mma16816(dd[s][2 * p + 1], aH[s], bh + 2);
                }
#pragma unroll
                for (int s = 0; s < 2; s++) {
                    mma16816(dd[s][2 * p + 0], aL[s], bh);
                    mma16816(dd[s][2 * p + 1], aL[s], bh + 2);
                }
            }
        }
        __syncthreads();
    }

    // epilogue: atomic accumulate
#pragma unroll
    for (int s = 0; s < 2; s++) {
#pragma unroll
        for (int half = 0; half < 2; half++) {
            int rl = mr + s * 16 + g + half * 8;
            int r = m0 + rl;
            if (r < cnt) {
                int tok = stok[rl];
#pragma unroll
                for (int nn = 0; nn < 4; nn++) {
                    int col = n0 + nc + nn * 8 + 2 * t4;
                    float* orow = out + (size_t)tok * H_DIM + col;
                    atomicAdd(&orow[0], dd[s][nn][half * 2 + 0]);
                    atomicAdd(&orow[1], dd[s][nn][half * 2 + 1]);
                }
            }
        }
    }
#undef DN_ISSUE
}

// ---------------- launch ----------------
extern "C" void kernel_launch(void* const* d_in, const int* in_sizes, int n_in,
                              void* d_out, int out_size) {
    const float* hs    = (const float*)d_in[0];
    const float* gw    = (const float*)d_in[1];
    const float* wgate = (const float*)d_in[2];
    const float* wup   = (const float*)d_in[3];
    const float* wdown = (const float*)d_in[4];
    float* out = (float*)d_out;

    cudaFuncSetAttribute(gateup_mma_kernel, cudaFuncAttributeMaxDynamicSharedMemorySize, GU_SMEM);
    cudaFuncSetAttribute(down_mma_kernel,   cudaFuncAttributeMaxDynamicSharedMemorySize, DN_SMEM);

    cudaMemsetAsync(d_out, 0, (size_t)out_size * sizeof(float));
    conv_w_kernel<<<2048, 256>>>(wgate, wup, wdown);
    conv_hs_kernel<<<512, 256>>>(hs);
    router_kernel<<<T_TOK, 128>>>(hs, gw);
    dispatch_kernel<<<1, 256>>>();
    gateup_mma_kernel<<<dim3(I_DIM / 64, T_TOK / 128, E_NUM), 256, GU_SMEM>>>();
    down_mma_kernel  <<<dim3(H_DIM / 64, T_TOK / 128, E_NUM), 256, DN_SMEM>>>(out);
}

// round 9
// speedup vs baseline: 3.9060x; 1.4076x over previous
#include <cuda_runtime.h>
#include <cuda_fp16.h>
#include <math.h>
#include <stdint.h>

#define T_TOK 2048
#define H_DIM 2048
#define E_NUM 32
#define I_DIM 768
#define TOPK  8
#define NASSIGN (T_TOK * TOPK)
#define NW ((size_t)E_NUM * I_DIM * H_DIM)

// ---------------- scratch ----------------
__device__ int   g_topk_id[T_TOK][TOPK];
__device__ float g_topk_w[T_TOK][TOPK];
__device__ int   g_cnt[E_NUM];
__device__ int   g_off[E_NUM + 1];
__device__ int   g_slot_tok[NASSIGN];
__device__ float g_slot_w[NASSIGN];
__device__ __half g_wg_h[NW];
__device__ __half g_wu_h[NW];
__device__ __half g_wd_h[NW];
__device__ __half g_hs_h[(size_t)T_TOK * H_DIM];
__device__ __half g_act_h[NASSIGN][I_DIM];

// ---------------- PTX helpers ----------------
__device__ __forceinline__ void mma16816(float* d, const uint32_t* a, const uint32_t* b) {
    asm volatile(
        "mma.sync.aligned.m16n8k16.row.col.f32.f16.f16.f32 "
        "{%0,%1,%2,%3}, {%4,%5,%6,%7}, {%8,%9}, {%0,%1,%2,%3};"
        : "+f"(d[0]), "+f"(d[1]), "+f"(d[2]), "+f"(d[3])
        : "r"(a[0]), "r"(a[1]), "r"(a[2]), "r"(a[3]), "r"(b[0]), "r"(b[1]));
}
#define LDMX4(r, addr) \
    asm volatile("ldmatrix.sync.aligned.m8n8.x4.shared.b16 {%0,%1,%2,%3}, [%4];" \
        : "=r"((r)[0]), "=r"((r)[1]), "=r"((r)[2]), "=r"((r)[3]) : "r"(addr))
#define CP16(dst, src) \
    asm volatile("cp.async.cg.shared.global [%0], [%1], 16;" :: "r"(dst), "l"(src))
#define CP_COMMIT() asm volatile("cp.async.commit_group;" ::: "memory")
#define CP_WAIT1()  asm volatile("cp.async.wait_group 1;" ::: "memory")
#define CP_WAIT0()  asm volatile("cp.async.wait_group 0;" ::: "memory")

__device__ __forceinline__ uint32_t smem_u32(const void* p) {
    return (uint32_t)__cvta_generic_to_shared(p);
}

// ---------------- weight convert: fp32 -> fp16 ----------------
__global__ void conv_w_kernel(const float* __restrict__ wg,
                              const float* __restrict__ wu,
                              const float* __restrict__ wd) {
    size_t total8 = (3 * NW) / 8;
    for (size_t i = (size_t)blockIdx.x * blockDim.x + threadIdx.x; i < total8;
         i += (size_t)gridDim.x * blockDim.x) {
        size_t e8 = i * 8;
        const float* src; __half* dst;
        if (e8 < NW)          { src = wg + e8;          dst = g_wg_h + e8; }
        else if (e8 < 2 * NW) { src = wu + (e8 - NW);   dst = g_wu_h + (e8 - NW); }
        else                  { src = wd + (e8 - 2*NW); dst = g_wd_h + (e8 - 2*NW); }
        float4 v0 = *(const float4*)src;
        float4 v1 = *(const float4*)(src + 4);
        __half2 h0 = __floats2half2_rn(v0.x, v0.y);
        __half2 h1 = __floats2half2_rn(v0.z, v0.w);
        __half2 h2 = __floats2half2_rn(v1.x, v1.y);
        __half2 h3 = __floats2half2_rn(v1.z, v1.w);
        uint4 o;
        o.x = *(uint32_t*)&h0; o.y = *(uint32_t*)&h1;
        o.z = *(uint32_t*)&h2; o.w = *(uint32_t*)&h3;
        *(uint4*)dst = o;
    }
}

// ---------------- hidden convert: fp32 -> fp16 (+ zero g_cnt) ---------------
__global__ void conv_hs_kernel(const float* __restrict__ hs) {
    if (blockIdx.x == 0 && threadIdx.x < E_NUM) g_cnt[threadIdx.x] = 0;
    size_t total8 = (size_t)T_TOK * H_DIM / 8;
    for (size_t i = (size_t)blockIdx.x * blockDim.x + threadIdx.x; i < total8;
         i += (size_t)gridDim.x * blockDim.x) {
        const float* src = hs + i * 8;
        float4 v0 = *(const float4*)src;
        float4 v1 = *(const float4*)(src + 4);
        __half2 h0 = __floats2half2_rn(v0.x, v0.y);
        __half2 h1 = __floats2half2_rn(v0.z, v0.w);
        __half2 h2 = __floats2half2_rn(v1.x, v1.y);
        __half2 h3 = __floats2half2_rn(v1.z, v1.w);
        uint4 o;
        o.x = *(uint32_t*)&h0; o.y = *(uint32_t*)&h1;
        o.z = *(uint32_t*)&h2; o.w = *(uint32_t*)&h3;
        *(uint4*)&g_hs_h[i * 8] = o;
    }
}

// ---------------- router ----------------
__global__ void router_kernel(const float* __restrict__ hs, const float* __restrict__ gw) {
    int t = blockIdx.x;
    __shared__ float part[128][E_NUM];
    __shared__ float sl[E_NUM];
    float acc[E_NUM];
#pragma unroll
    for (int e = 0; e < E_NUM; e++) acc[e] = 0.f;
    const float* hrow = hs + (size_t)t * H_DIM;
    for (int h = threadIdx.x; h < H_DIM; h += 128) {
        float x = hrow[h];
#pragma unroll
        for (int e = 0; e < E_NUM; e++) acc[e] += x * gw[e * H_DIM + h];
    }
#pragma unroll
    for (int e = 0; e < E_NUM; e++) part[threadIdx.x][e] = acc[e];
    __syncthreads();
    if (threadIdx.x < E_NUM) {
        float s = 0.f;
        for (int i = 0; i < 128; i++) s += part[i][threadIdx.x];
        sl[threadIdx.x] = s;
    }
    __syncthreads();
    if (threadIdx.x == 0) {
        unsigned mask = 0;
        int ids[TOPK]; float lv[TOPK];
        for (int k = 0; k < TOPK; k++) {
            float best = -3.4e38f; int bi = 0;
            for (int e = 0; e < E_NUM; e++)
                if (!((mask >> e) & 1u) && sl[e] > best) { best = sl[e]; bi = e; }
            mask |= (1u << bi); ids[k] = bi; lv[k] = best;
        }
        float mx = lv[0], s = 0.f, w[TOPK];
        for (int k = 0; k < TOPK; k++) { w[k] = expf(lv[k] - mx); s += w[k]; }
        float inv = 1.f / s;
        for (int k = 0; k < TOPK; k++) {
            g_topk_id[t][k] = ids[k];
            g_topk_w[t][k]  = w[k] * inv;
            atomicAdd(&g_cnt[ids[k]], 1);
        }
    }
}

// ---------------- fused scan + scatter ----------------
__global__ void dispatch_kernel() {
    __shared__ int soff[E_NUM];
    __shared__ int scur[E_NUM];
    int tid = threadIdx.x;
    if (tid < E_NUM) scur[tid] = 0;
    if (tid == 0) {
        int s = 0;
        for (int e = 0; e < E_NUM; e++) { g_off[e] = s; soff[e] = s; s += g_cnt[e]; }
        g_off[E_NUM] = s;
    }
    __syncthreads();
    for (int t = tid; t < T_TOK; t += 256) {
#pragma unroll
        for (int k = 0; k < TOPK; k++) {
            int e = g_topk_id[t][k];
            int p = atomicAdd(&scur[e], 1);
            int s = soff[e] + p;
            g_slot_tok[s] = t;
            g_slot_w[s]  = g_topk_w[t][k];
        }
    }
}

// ============ gate-up GEMM: single-term fp16, 3-stage cp.async ==============
// stage (bytes): A 0 (128x80=10240) | B_G 10240 (64x80=5120) | B_U 15360
#define GU_STAGE 20480
#define GU_META  (3 * GU_STAGE)
#define GU_SMEM  (GU_META + 1024)
#define GU_NCH   (H_DIM / 32)

__global__ __launch_bounds__(256, 2) void gateup_mma_kernel() {
    int e = blockIdx.z;
    int cnt = g_cnt[e];
    int m0 = blockIdx.y * 128;
    if (m0 >= cnt) return;
    int base = g_off[e];
    int n0 = blockIdx.x * 64;

    extern __shared__ char smem[];
    uint32_t sb = smem_u32(smem);
    int tid = threadIdx.x, wid = tid >> 5, lane = tid & 31;
    int g = lane >> 2, t4 = lane & 3;

    int*   stok = (int*)(smem + GU_META);
    float* swt  = (float*)(smem + GU_META + 512);
    if (tid < 128) {
        int r = m0 + tid;
        int rc = (r < cnt) ? r : (cnt - 1);
        stok[tid] = g_slot_tok[base + rc];
        swt[tid]  = (r < cnt) ? g_slot_w[base + rc] : 0.f;
    }
    __syncthreads();

    int lr = tid >> 1, asel = tid & 1;                 // A: 2 thr/row, 32B each
    const __half* a_src = g_hs_h + (size_t)stok[lr] * H_DIM + asel * 16;
    uint32_t aDst = sb + (uint32_t)(lr * 80 + asel * 32);
    int bt = tid & 127, br = bt >> 1, bsel = bt & 1;   // B: 2 thr/row, 32B each
    const __half* b_src = ((tid >= 128) ? g_wu_h : g_wg_h)
                          + ((size_t)e * I_DIM + n0 + br) * H_DIM + bsel * 16;
    uint32_t bDst = sb + 10240u + (tid >= 128 ? 5120u : 0u) + (uint32_t)(br * 80 + bsel * 32);

    int quad = lane >> 3, r8 = lane & 7;
    int aRow = (quad & 1) * 8 + r8, aCol = (quad >> 1) * 8;
    int bRow = (quad >> 1) * 8 + r8, bCol = (quad & 1) * 8;
    int mr = (wid & 3) * 32, nc = (wid >> 2) * 32;
    uint32_t aBase = sb + (uint32_t)((mr + aRow) * 80 + aCol * 2);
    uint32_t bBase = sb + 10240u + (uint32_t)((nc + bRow) * 80 + bCol * 2);

    float ag[2][4][4] = {}, au[2][4][4] = {};

#define GU_ISSUE(i) do { \
    uint32_t so = (uint32_t)((i) % 3) * GU_STAGE; \
    int k0 = (i) * 32; \
    CP16(aDst + so,      (const char*)(a_src + k0)); \
    CP16(aDst + so + 16, (const char*)(a_src + k0 + 8)); \
    CP16(bDst + so,      (const char*)(b_src + k0)); \
    CP16(bDst + so + 16, (const char*)(b_src + k0 + 8)); \
    CP_COMMIT(); \
} while (0)

    GU_ISSUE(0);
    GU_ISSUE(1);

    for (int i = 0; i < GU_NCH; i++) {
        if (i + 1 < GU_NCH) CP_WAIT1(); else CP_WAIT0();
        __syncthreads();
        if (i + 2 < GU_NCH) GU_ISSUE(i + 2);
        uint32_t so = (uint32_t)(i % 3) * GU_STAGE;
#pragma unroll
        for (int kb = 0; kb < 2; kb++) {
            uint32_t aH[2][4];
            uint32_t aA = aBase + so + kb * 32;
            LDMX4(aH[0], aA);
            LDMX4(aH[1], aA + 16 * 80);
#pragma unroll
            for (int p = 0; p < 2; p++) {
                uint32_t bg[4], bu[4];
                uint32_t bA = bBase + so + p * 16 * 80 + kb * 32;
                LDMX4(bg, bA);
                LDMX4(bu, bA + 5120);
#pragma unroll
                for (int s = 0; s < 2; s++) {
                    mma16816(ag[s][2 * p + 0], aH[s], bg);
                    mma16816(ag[s][2 * p + 1], aH[s], bg + 2);
                    mma16816(au[s][2 * p + 0], aH[s], bu);
                    mma16816(au[s][2 * p + 1], aH[s], bu + 2);
                }
            }
        }
        __syncthreads();
    }

    // epilogue: silu(g)*u*route_w -> fp16 act scratch
#pragma unroll
    for (int s = 0; s < 2; s++) {
#pragma unroll
        for (int half = 0; half < 2; half++) {
            int rl = mr + s * 16 + g + half * 8;
            int r = m0 + rl;
            if (r < cnt) {
                float w = swt[rl];
                size_t slot = (size_t)(base + r);
#pragma unroll
                for (int nn = 0; nn < 4; nn++) {
                    float gv0 = ag[s][nn][half * 2 + 0], gv1 = ag[s][nn][half * 2 + 1];
                    float uv0 = au[s][nn][half * 2 + 0], uv1 = au[s][nn][half * 2 + 1];
                    float a0 = (gv0 / (1.f + expf(-gv0))) * uv0 * w;
                    float a1 = (gv1 / (1.f + expf(-gv1))) * uv1 * w;
                    __half2 hp = __floats2half2_rn(a0, a1);
                    int col = n0 + nc + nn * 8 + 2 * t4;
                    *(uint32_t*)&g_act_h[slot][col] = *(uint32_t*)&hp;
                }
            }
        }
    }
#undef GU_ISSUE
}

// ============ down GEMM: single-term fp16, 3-stage cp.async =================
// stage: A 0 (10240) | B 10240 (5120) ; STAGE 15360
#define DN_STAGE 15360
#define DN_META  (3 * DN_STAGE)
#define DN_SMEM  (DN_META + 512)
#define DN_NCH   (I_DIM / 32)

__global__ __launch_bounds__(256, 2) void down_mma_kernel(float* __restrict__ out) {
    int e = blockIdx.z;
    int cnt = g_cnt[e];
    int m0 = blockIdx.y * 128;
    if (m0 >= cnt) return;
    int base = g_off[e];
    int n0 = blockIdx.x * 64;

    extern __shared__ char smem[];
    uint32_t sb = smem_u32(smem);
    int tid = threadIdx.x, wid = tid >> 5, lane = tid & 31;
    int g = lane >> 2, t4 = lane & 3;

    int* stok = (int*)(smem + DN_META);
    if (tid < 128) {
        int r = m0 + tid;
        stok[tid] = (r < cnt) ? g_slot_tok[base + r] : 0;
    }
    __syncthreads();

    int lr = tid >> 1, asel = tid & 1;
    int arow_idx = base + min(m0 + lr, cnt - 1);
    const __half* a_src = &g_act_h[arow_idx][asel * 16];
    uint32_t aDst = sb + (uint32_t)(lr * 80 + asel * 32);
    int br = tid >> 2, bsel = tid & 3;
    const __half* b_src = g_wd_h + ((size_t)e * H_DIM + n0 + br) * I_DIM + bsel * 8;
    uint32_t bDst = sb + 10240u + (uint32_t)(br * 80 + bsel * 16);

    int quad = lane >> 3, r8 = lane & 7;
    int aRow = (quad & 1) * 8 + r8, aCol = (quad >> 1) * 8;
    int bRow = (quad >> 1) * 8 + r8, bCol = (quad & 1) * 8;
    int mr = (wid & 3) * 32, nc = (wid >> 2) * 32;
    uint32_t aBase = sb + (uint32_t)((mr + aRow) * 80 + aCol * 2);
    uint32_t bBase = sb + 10240u + (uint32_t)((nc + bRow) * 80 + bCol * 2);

    float dd[2][4][4] = {};

#define DN_ISSUE(i) do { \
    uint32_t so = (uint32_t)((i) % 3) * DN_STAGE; \
    int k0 = (i) * 32; \
    CP16(aDst + so,      (const char*)(a_src + k0)); \
    CP16(aDst + so + 16, (const char*)(a_src + k0 + 8)); \
    CP16(bDst + so,      (const char*)(b_src + k0)); \
    CP_COMMIT(); \
} while (0)

    DN_ISSUE(0);
    DN_ISSUE(1);

    for (int i = 0; i < DN_NCH; i++) {
        if (i + 1 < DN_NCH) CP_WAIT1(); else CP_WAIT0();
        __syncthreads();
        if (i + 2 < DN_NCH) DN_ISSUE(i + 2);
        uint32_t so = (uint32_t)(i % 3) * DN_STAGE;
#pragma unroll
        for (int kb = 0; kb < 2; kb++) {
            uint32_t aH[2][4];
            uint32_t aA = aBase + so + kb * 32;
            LDMX4(aH[0], aA);
            LDMX4(aH[1], aA + 16 * 80);
#pragma unroll
            for (int p = 0; p < 2; p++) {
                uint32_t bh[4];
                uint32_t bA = bBase + so + p * 16 * 80 + kb * 32;
                LDMX4(bh, bA);
#pragma unroll
                for (int s = 0; s < 2; s++) {
                    mma16816(dd[s][2 * p + 0], aH[s], bh);
                    mma16816(dd[s][2 * p + 1], aH[s], bh + 2);
                }
            }
        }
        __syncthreads();
    }

    // epilogue: atomic accumulate
#pragma unroll
    for (int s = 0; s < 2; s++) {
#pragma unroll
        for (int half = 0; half < 2; half++) {
            int rl = mr + s * 16 + g + half * 8;
            int r = m0 + rl;
            if (r < cnt) {
                int tok = stok[rl];
#pragma unroll
                for (int nn = 0; nn < 4; nn++) {
                    int col = n0 + nc + nn * 8 + 2 * t4;
                    float* orow = out + (size_t)tok * H_DIM + col;
                    atomicAdd(&orow[0], dd[s][nn][half * 2 + 0]);
                    atomicAdd(&orow[1], dd[s][nn][half * 2 + 1]);
                }
            }
        }
    }
#undef DN_ISSUE
}

// ---------------- launch ----------------
extern "C" void kernel_launch(void* const* d_in, const int* in_sizes, int n_in,
                              void* d_out, int out_size) {
    const float* hs    = (const float*)d_in[0];
    const float* gw    = (const float*)d_in[1];
    const float* wgate = (const float*)d_in[2];
    const float* wup   = (const float*)d_in[3];
    const float* wdown = (const float*)d_in[4];
    float* out = (float*)d_out;

    cudaFuncSetAttribute(gateup_mma_kernel, cudaFuncAttributeMaxDynamicSharedMemorySize, GU_SMEM);
    cudaFuncSetAttribute(down_mma_kernel,   cudaFuncAttributeMaxDynamicSharedMemorySize, DN_SMEM);

    cudaMemsetAsync(d_out, 0, (size_t)out_size * sizeof(float));
    conv_w_kernel<<<2048, 256>>>(wgate, wup, wdown);
    conv_hs_kernel<<<512, 256>>>(hs);
    router_kernel<<<T_TOK, 128>>>(hs, gw);
    dispatch_kernel<<<1, 256>>>();
    gateup_mma_kernel<<<dim3(I_DIM / 64, T_TOK / 128, E_NUM), 256, GU_SMEM>>>();
    down_mma_kernel  <<<dim3(H_DIM / 64, T_TOK / 128, E_NUM), 256, DN_SMEM>>>(out);
}